// round 1
// baseline (speedup 1.0000x reference)
#include <cuda_runtime.h>
#include <math.h>

// Problem constants (V2VNet_35373350650590):
// B=2, A=5, C=64, H=W=128, gnn_iter=2
#define NB   2
#define NA   5
#define BA   10      // B*A
#define NC   64
#define HH   128
#define WW   128
#define HW   16384   // H*W
#define C2   128     // 2*C
#define NO   192     // 3*C output channels of gate conv
#define KK   1152    // 2C * 9 reduction dim

// ---------------- static scratch (no allocations allowed) ----------------
__device__ float g_mean [(size_t)BA * NC * HW];   // ~42 MB
__device__ float g_feat [(size_t)BA * NC * HW];   // ~42 MB
__device__ float g_gates[(size_t)BA * NO * HW];   // ~126 MB

// =========================================================================
// Kernel 1: warp (rotate-resample then translate-resample) + masked mean.
// One CTA per (b, i, c). Loops j != i. Source plane and rotated intermediate
// both live in shared memory (row stride 129 to kill bank conflicts).
// mean[b,i,c] = (1/(A-1)) * sum_{j!=i} translate(rotate(feats[b,j,c]))
// =========================================================================
__global__ __launch_bounds__(512, 1)
void warp_mean_kernel(const float* __restrict__ feats,
                      const float* __restrict__ trans,
                      float* __restrict__ meanb)
{
    const int c  = blockIdx.x;          // 0..63
    const int bi = blockIdx.y;          // 0..9  (= b*A + i)
    const int b  = bi / NA;
    const int i  = bi - b * NA;

    extern __shared__ float sm[];
    float* s_src = sm;                  // 128 * 129
    float* s_f   = sm + HH * 129;       // 128 * 129

    const int tid = threadIdx.x;        // 512 threads, 32 px each

    float acc[32];
#pragma unroll
    for (int k = 0; k < 32; k++) acc[k] = 0.f;

    for (int j = 0; j < NA; j++) {
        if (j == i) continue;
        const float* tp = trans + (size_t)(bi * NA + j) * 16;
        const float t00 = tp[0], t01 = tp[1], t03 = tp[3];
        const float t10 = tp[4], t11 = tp[5], t13 = tp[7];

        // ---- load source plane feats[b, j, c] into smem ----
        const float* src = feats + ((size_t)(b * NA + j) * NC + c) * HW;
#pragma unroll
        for (int v = tid; v < HW / 4; v += 512) {
            float4 x = ((const float4*)src)[v];
            int r  = v >> 5;
            int c4 = (v & 31) << 2;
            float* d = s_src + r * 129 + c4;
            d[0] = x.x; d[1] = x.y; d[2] = x.z; d[3] = x.w;
        }
        __syncthreads();

        // ---- pass 1: rotation resample (pixel-space affine) ----
        // px = t00*(w-63.5) + t01*(h-63.5) + 63.5 ; py analogous
#pragma unroll 4
        for (int k = 0; k < 32; k++) {
            int p = tid + (k << 9);
            int h = p >> 7, w = p & 127;
            float wf = (float)w - 63.5f;
            float hf = (float)h - 63.5f;
            float px = fmaf(t00, wf, fmaf(t01, hf, 63.5f));
            float py = fmaf(t10, wf, fmaf(t11, hf, 63.5f));
            float x0f = floorf(px), y0f = floorf(py);
            int x0 = (int)x0f, y0 = (int)y0f;
            int x1 = x0 + 1,  y1 = y0 + 1;
            float fx = px - x0f, fy = py - y0f;
            float gx0 = 1.f - fx, gy0 = 1.f - fy;

            float mx0 = ((unsigned)x0 < 128u) ? 1.f : 0.f;
            float mx1 = ((unsigned)x1 < 128u) ? 1.f : 0.f;
            float my0 = ((unsigned)y0 < 128u) ? 1.f : 0.f;
            float my1 = ((unsigned)y1 < 128u) ? 1.f : 0.f;
            int xc0 = min(max(x0, 0), 127), xc1 = min(max(x1, 0), 127);
            int yc0 = min(max(y0, 0), 127), yc1 = min(max(y1, 0), 127);

            float v00 = s_src[yc0 * 129 + xc0] * (mx0 * my0);
            float v10 = s_src[yc0 * 129 + xc1] * (mx1 * my0);
            float v01 = s_src[yc1 * 129 + xc0] * (mx0 * my1);
            float v11 = s_src[yc1 * 129 + xc1] * (mx1 * my1);

            float f = v00 * (gx0 * gy0) + v10 * (fx * gy0)
                    + v01 * (gx0 * fy)  + v11 * (fx * fy);
            s_f[h * 129 + w] = f;
        }
        __syncthreads();

        // ---- pass 2: constant-shift translate resample, accumulate ----
        float tx = 2.f * t03;
        float ty = -2.f * t13;
        float itxf = floorf(tx), ityf = floorf(ty);
        int itx = (int)itxf, ity = (int)ityf;
        float fx = tx - itxf, fy = ty - ityf;
        float w00 = (1.f - fx) * (1.f - fy);
        float w10 = fx * (1.f - fy);
        float w01 = (1.f - fx) * fy;
        float w11 = fx * fy;
#pragma unroll
        for (int k = 0; k < 32; k++) {
            int p = tid + (k << 9);
            int h = p >> 7, w = p & 127;
            int x0 = w + itx, y0 = h + ity;
            int x1 = x0 + 1,  y1 = y0 + 1;
            float mx0 = ((unsigned)x0 < 128u) ? 1.f : 0.f;
            float mx1 = ((unsigned)x1 < 128u) ? 1.f : 0.f;
            float my0 = ((unsigned)y0 < 128u) ? 1.f : 0.f;
            float my1 = ((unsigned)y1 < 128u) ? 1.f : 0.f;
            int xc0 = min(max(x0, 0), 127), xc1 = min(max(x1, 0), 127);
            int yc0 = min(max(y0, 0), 127), yc1 = min(max(y1, 0), 127);

            float v00 = s_f[yc0 * 129 + xc0] * (mx0 * my0);
            float v10 = s_f[yc0 * 129 + xc1] * (mx1 * my0);
            float v01 = s_f[yc1 * 129 + xc0] * (mx0 * my1);
            float v11 = s_f[yc1 * 129 + xc1] * (mx1 * my1);

            acc[k] += v00 * w00 + v10 * w10 + v01 * w01 + v11 * w11;
        }
        __syncthreads();   // before overwriting s_src for next j
    }

    float* out = meanb + ((size_t)bi * NC + c) * HW;
#pragma unroll
    for (int k = 0; k < 32; k++)
        out[tid + (k << 9)] = acc[k] * 0.25f;   // / (A-1)
}

// =========================================================================
// Kernel 2: gate conv as implicit GEMM (fp32, CUDA cores).
// Per image n: Y[192, 16384] = W[192, 1152] x X[1152, 16384]
// where X[(c,ky,kx), (h,w)] = cat(feat,mean)[c, h+ky-1, w+kx-1] (zero pad).
// CTA tile: 64 outputs x 128 pixels (one image row). 256 threads, 8x4/thread.
// =========================================================================
__global__ __launch_bounds__(256, 3)
void conv_kernel(const float* __restrict__ feat,
                 const float* __restrict__ meanb,
                 const float* __restrict__ wx,
                 float* __restrict__ gates)
{
    const int h  = blockIdx.x;   // 0..127 (output row = pixel block)
    const int ob = blockIdx.y;   // 0..2   (64-output block)
    const int n  = blockIdx.z;   // 0..9

    __shared__ float As[16][68];     // [k][o], padded to break store conflicts
    __shared__ float Bs[16][128];    // [k][w]

    const int tid  = threadIdx.x;
    const int lane = tid & 31;
    const int wrp  = tid >> 5;

    float acc[8][4];
#pragma unroll
    for (int a = 0; a < 8; a++)
#pragma unroll
        for (int p = 0; p < 4; p++) acc[a][p] = 0.f;

    const float* wbase = wx + (size_t)(ob * 64) * KK;

    for (int kc = 0; kc < KK; kc += 16) {
        // ---- A tile: weights 64 x 16 (contiguous along k) ----
#pragma unroll
        for (int t = tid; t < 1024; t += 256) {
            int o  = t >> 4;
            int kk = t & 15;
            As[kk][o] = wbase[(size_t)o * KK + kc + kk];
        }
        // ---- B tile: on-the-fly im2col gather 16 x 128 ----
#pragma unroll
        for (int idx = tid; idx < 2048; idx += 256) {
            int kk = idx >> 7;
            int w  = idx & 127;
            int k  = kc + kk;
            int cc  = k / 9;
            int tap = k - cc * 9;
            int ty  = tap / 3;
            int dy  = ty - 1;
            int dx  = tap - ty * 3 - 1;
            int hh = h + dy, ww = w + dx;
            float v = 0.f;
            if ((unsigned)hh < 128u && (unsigned)ww < 128u) {
                const float* src = (cc < NC)
                    ? (feat  + (((size_t)n * NC + cc)      << 14))
                    : (meanb + (((size_t)n * NC + cc - NC) << 14));
                v = src[(hh << 7) + ww];
            }
            Bs[kk][w] = v;
        }
        __syncthreads();

#pragma unroll
        for (int kk = 0; kk < 16; kk++) {
            float4 a0 = *(const float4*)&As[kk][wrp * 8];
            float4 a1 = *(const float4*)&As[kk][wrp * 8 + 4];
            float4 bb = *(const float4*)&Bs[kk][lane * 4];
            float av[8] = {a0.x, a0.y, a0.z, a0.w, a1.x, a1.y, a1.z, a1.w};
            float bv[4] = {bb.x, bb.y, bb.z, bb.w};
#pragma unroll
            for (int oo = 0; oo < 8; oo++)
#pragma unroll
                for (int pp = 0; pp < 4; pp++)
                    acc[oo][pp] = fmaf(av[oo], bv[pp], acc[oo][pp]);
        }
        __syncthreads();
    }

    // write raw gate pre-activations: gates[n][ob*64 + wrp*8 + oo][h][w]
#pragma unroll
    for (int oo = 0; oo < 8; oo++) {
        size_t off = (((size_t)n * NO + ob * 64 + wrp * 8 + oo) << 14)
                   + (h << 7) + lane * 4;
        *(float4*)(gates + off) =
            make_float4(acc[oo][0], acc[oo][1], acc[oo][2], acc[oo][3]);
    }
}

// =========================================================================
// Kernel 3: ConvGRU gating (h0 = 0):
// r = sigm(xr+bx_r+bh_r), z = sigm(xz+bx_z+bh_z), n = tanh(xn+bx_n + r*bh_n)
// out = (1-z)*n
// =========================================================================
__global__ __launch_bounds__(256)
void gate_kernel(const float* __restrict__ gates,
                 const float* __restrict__ bx,
                 const float* __restrict__ bh,
                 float* __restrict__ out)
{
    int p = blockIdx.x * 256 + threadIdx.x;      // 0 .. 10485759
    int n   = p >> 20;           // / (64*16384)
    int cc  = (p >> 14) & 63;
    int pix = p & 16383;
    size_t g0 = (((size_t)n * NO + cc) << 14) + pix;

    float xr = gates[g0]                        + bx[cc];
    float xz = gates[g0 + ((size_t)64  << 14)]  + bx[cc + 64];
    float xn = gates[g0 + ((size_t)128 << 14)]  + bx[cc + 128];

    float r  = 1.f / (1.f + expf(-(xr + bh[cc])));
    float z  = 1.f / (1.f + expf(-(xz + bh[cc + 64])));
    float nn = tanhf(xn + r * bh[cc + 128]);
    out[p] = (1.f - z) * nn;
}

// =========================================================================
extern "C" void kernel_launch(void* const* d_in, const int* in_sizes, int n_in,
                              void* d_out, int out_size)
{
    const float* feats = (const float*)d_in[0];   // [2,5,64,128,128]
    const float* trans = (const float*)d_in[1];   // [2,5,5,4,4]
    const float* wx    = (const float*)d_in[2];   // [192,128,3,3]
    const float* bx    = (const float*)d_in[4];   // [192]
    const float* bh    = (const float*)d_in[5];   // [192]
    float* out = (float*)d_out;                   // [2,5,64,128,128]

    float *pm, *pf, *pg;
    cudaGetSymbolAddress((void**)&pm, g_mean);
    cudaGetSymbolAddress((void**)&pf, g_feat);
    cudaGetSymbolAddress((void**)&pg, g_gates);

    const int smem = 2 * HH * 129 * (int)sizeof(float);   // 132096 B
    cudaFuncSetAttribute(warp_mean_kernel,
                         cudaFuncAttributeMaxDynamicSharedMemorySize, smem);

    for (int it = 0; it < 2; it++) {
        const float* fin  = (it == 0) ? feats : pf;
        float*       fout = (it == 1) ? out   : pf;

        warp_mean_kernel<<<dim3(NC, BA), 512, smem>>>(fin, trans, pm);
        conv_kernel<<<dim3(HH, 3, BA), 256>>>(fin, pm, wx, pg);
        gate_kernel<<<(BA * NC * HW) / 256, 256>>>(pg, bx, bh, fout);
    }
}

// round 3
// speedup vs baseline: 4.8153x; 4.8153x over previous
#include <cuda_runtime.h>
#include <cuda_fp16.h>
#include <math.h>
#include <cstdint>

// Problem constants (V2VNet_35373350650590):
// B=2, A=5, C=64, H=W=128, gnn_iter=2
#define NB   2
#define NA   5
#define BA   10      // B*A
#define NC   64
#define HH   128
#define WW   128
#define HW   16384   // H*W
#define NO   192     // 3*C output channels of gate conv
#define KK   1152    // 2C * 9 reduction dim

// ---------------- static scratch (no allocations allowed) ----------------
__device__ float  g_mean[(size_t)BA * NC * HW];   // ~42 MB
__device__ float  g_feat[(size_t)BA * NC * HW];   // ~42 MB
__device__ __half g_wt  [(size_t)NO * KK];        // fp16 weights, tap-major K

// ======================= PTX helpers (portable) ==========================
__device__ __forceinline__ uint32_t smem_to_u32(const void* p) {
    uint32_t a;
    asm("{ .reg .u64 t; cvta.to.shared.u64 t, %1; cvt.u32.u64 %0, t; }"
        : "=r"(a) : "l"(p));
    return a;
}
#define LDMATRIX_X4(r0, r1, r2, r3, addr) \
    asm volatile("ldmatrix.sync.aligned.m8n8.x4.shared.b16 {%0,%1,%2,%3}, [%4];" \
        : "=r"(r0), "=r"(r1), "=r"(r2), "=r"(r3) : "r"(addr))
#define MMA16816(c, a, b0, b1) \
    asm volatile("mma.sync.aligned.m16n8k16.row.col.f32.f16.f16.f32 " \
        "{%0,%1,%2,%3}, {%4,%5,%6,%7}, {%8,%9}, {%0,%1,%2,%3};" \
        : "+f"((c)[0]), "+f"((c)[1]), "+f"((c)[2]), "+f"((c)[3]) \
        : "r"((a)[0]), "r"((a)[1]), "r"((a)[2]), "r"((a)[3]), \
          "r"(b0), "r"(b1))
#define STS32(addr, v) \
    asm volatile("st.shared.b32 [%0], %1;" :: "r"(addr), "r"(v) : "memory")
#define STS128(addr, a, b, c, d) \
    asm volatile("st.shared.v4.b32 [%0], {%1, %2, %3, %4};" \
        :: "r"(addr), "r"(a), "r"(b), "r"(c), "r"(d) : "memory")

// =========================================================================
// Kernel 0: weight transpose + fp16 round.
// wt[o][tap*128 + cc] = half(wx[o][cc][tap])   (K reordered to tap-major)
// =========================================================================
__global__ __launch_bounds__(256)
void wtrans_kernel(const float* __restrict__ wx, __half* __restrict__ wt)
{
    int idx = blockIdx.x * 256 + threadIdx.x;
    if (idx >= NO * KK) return;
    int o = idx / KK;
    int rem = idx - o * KK;
    int tap = rem >> 7;
    int cc  = rem & 127;
    wt[idx] = __float2half_rn(wx[o * KK + cc * 9 + tap]);
}

// =========================================================================
// Kernel 1: warp (rotate-resample then translate-resample) + masked mean.
// One CTA per (b, i, c). Source and rotated plane live in shared memory.
// (unchanged from round 1 — validated at rel_err 2.9e-6, 186us)
// =========================================================================
__global__ __launch_bounds__(512, 1)
void warp_mean_kernel(const float* __restrict__ feats,
                      const float* __restrict__ trans,
                      float* __restrict__ meanb)
{
    const int c  = blockIdx.x;
    const int bi = blockIdx.y;
    const int b  = bi / NA;
    const int i  = bi - b * NA;

    extern __shared__ float sm[];
    float* s_src = sm;
    float* s_f   = sm + HH * 129;

    const int tid = threadIdx.x;

    float acc[32];
#pragma unroll
    for (int k = 0; k < 32; k++) acc[k] = 0.f;

    for (int j = 0; j < NA; j++) {
        if (j == i) continue;
        const float* tp = trans + (size_t)(bi * NA + j) * 16;
        const float t00 = tp[0], t01 = tp[1], t03 = tp[3];
        const float t10 = tp[4], t11 = tp[5], t13 = tp[7];

        const float* src = feats + ((size_t)(b * NA + j) * NC + c) * HW;
#pragma unroll
        for (int v = tid; v < HW / 4; v += 512) {
            float4 x = ((const float4*)src)[v];
            int r  = v >> 5;
            int c4 = (v & 31) << 2;
            float* d = s_src + r * 129 + c4;
            d[0] = x.x; d[1] = x.y; d[2] = x.z; d[3] = x.w;
        }
        __syncthreads();

#pragma unroll 4
        for (int k = 0; k < 32; k++) {
            int p = tid + (k << 9);
            int h = p >> 7, w = p & 127;
            float wf = (float)w - 63.5f;
            float hf = (float)h - 63.5f;
            float px = fmaf(t00, wf, fmaf(t01, hf, 63.5f));
            float py = fmaf(t10, wf, fmaf(t11, hf, 63.5f));
            float x0f = floorf(px), y0f = floorf(py);
            int x0 = (int)x0f, y0 = (int)y0f;
            int x1 = x0 + 1,  y1 = y0 + 1;
            float fx = px - x0f, fy = py - y0f;
            float gx0 = 1.f - fx, gy0 = 1.f - fy;

            float mx0 = ((unsigned)x0 < 128u) ? 1.f : 0.f;
            float mx1 = ((unsigned)x1 < 128u) ? 1.f : 0.f;
            float my0 = ((unsigned)y0 < 128u) ? 1.f : 0.f;
            float my1 = ((unsigned)y1 < 128u) ? 1.f : 0.f;
            int xc0 = min(max(x0, 0), 127), xc1 = min(max(x1, 0), 127);
            int yc0 = min(max(y0, 0), 127), yc1 = min(max(y1, 0), 127);

            float v00 = s_src[yc0 * 129 + xc0] * (mx0 * my0);
            float v10 = s_src[yc0 * 129 + xc1] * (mx1 * my0);
            float v01 = s_src[yc1 * 129 + xc0] * (mx0 * my1);
            float v11 = s_src[yc1 * 129 + xc1] * (mx1 * my1);

            float f = v00 * (gx0 * gy0) + v10 * (fx * gy0)
                    + v01 * (gx0 * fy)  + v11 * (fx * fy);
            s_f[h * 129 + w] = f;
        }
        __syncthreads();

        float tx = 2.f * t03;
        float ty = -2.f * t13;
        float itxf = floorf(tx), ityf = floorf(ty);
        int itx = (int)itxf, ity = (int)ityf;
        float fx = tx - itxf, fy = ty - ityf;
        float w00 = (1.f - fx) * (1.f - fy);
        float w10 = fx * (1.f - fy);
        float w01 = (1.f - fx) * fy;
        float w11 = fx * fy;
#pragma unroll
        for (int k = 0; k < 32; k++) {
            int p = tid + (k << 9);
            int h = p >> 7, w = p & 127;
            int x0 = w + itx, y0 = h + ity;
            int x1 = x0 + 1,  y1 = y0 + 1;
            float mx0 = ((unsigned)x0 < 128u) ? 1.f : 0.f;
            float mx1 = ((unsigned)x1 < 128u) ? 1.f : 0.f;
            float my0 = ((unsigned)y0 < 128u) ? 1.f : 0.f;
            float my1 = ((unsigned)y1 < 128u) ? 1.f : 0.f;
            int xc0 = min(max(x0, 0), 127), xc1 = min(max(x1, 0), 127);
            int yc0 = min(max(y0, 0), 127), yc1 = min(max(y1, 0), 127);

            float v00 = s_f[yc0 * 129 + xc0] * (mx0 * my0);
            float v10 = s_f[yc0 * 129 + xc1] * (mx1 * my0);
            float v01 = s_f[yc1 * 129 + xc0] * (mx0 * my1);
            float v11 = s_f[yc1 * 129 + xc1] * (mx1 * my1);

            acc[k] += v00 * w00 + v10 * w10 + v01 * w01 + v11 * w11;
        }
        __syncthreads();
    }

    float* out = meanb + ((size_t)bi * NC + c) * HW;
#pragma unroll
    for (int k = 0; k < 32; k++)
        out[tid + (k << 9)] = acc[k] * 0.25f;
}

// =========================================================================
// Kernel 2: conv as implicit GEMM (fp16 mma.sync m16n8k16, fp32 accum)
// + fused ConvGRU gating.
// Per CTA: one image row h => D[128 px, 192 outch]. K=1152 in 36 stages
// of 32 (tap-major => one (dy,dx) shift per stage), double-buffered SMEM.
// 8 warps: warp grid 2(m) x 4(n), warp tile 64 px x 48 ch.
// SMEM stage: A 128 rows x 80B (32 halves + pad), B 192 rows x 80B.
// Epilogue: C frags -> smem (stride 193) -> cross-warp gate -> out.
// =========================================================================
#define AROW      80u
#define STAGE_A   (128u * AROW)           // 10240
#define STAGE_B   (192u * AROW)           // 15360
#define STAGE_SZ  (STAGE_A + STAGE_B)     // 25600
#define EPI_STRIDE 193
#define CONV_SMEM  (128 * EPI_STRIDE * 4) // 98816 >= 2*STAGE_SZ (51200)

__global__ __launch_bounds__(256, 1)
void conv_gate_kernel(const float* __restrict__ feat,
                      const float* __restrict__ meanb,
                      const __half* __restrict__ wt,
                      const float* __restrict__ bx,
                      const float* __restrict__ bh,
                      float* __restrict__ out)
{
    extern __shared__ char smemraw[];
    const uint32_t sbase = smem_to_u32(smemraw);
    float* sepi = (float*)smemraw;

    const int tid  = threadIdx.x;
    const int wid  = tid >> 5;
    const int lane = tid & 31;
    const int h = blockIdx.x;     // image row 0..127
    const int n = blockIdx.y;     // image 0..9

    const int wm = wid & 1;       // m(warp) -> w offset wm*64
    const int wn = wid >> 1;      // n(warp) -> ch offset wn*48

    float c[4][6][4];
#pragma unroll
    for (int mt = 0; mt < 4; mt++)
#pragma unroll
        for (int nt = 0; nt < 6; nt++)
#pragma unroll
            for (int r = 0; r < 4; r++) c[mt][nt][r] = 0.f;

    // ---------------- stage loaders ----------------
    // A: 128(m=w) x 32(k) halves; element e: m = e&127, kpair kp = e>>7 (0..15)
    // B: 192(o) x 32(k) halves as float4 chunks: o = idx>>2, q = idx&3
    uint32_t  areg[8];
    float4    breg[3];

    auto ldg_stage = [&](int kb) {
        const int tap = kb >> 2;
        const int ty  = tap / 3;
        const int dy  = ty - 1;
        const int dx  = tap - ty * 3 - 1;
        const int cc0 = (kb & 3) * 32;
        const float* reg0 = (cc0 < 64) ? feat : meanb;
        const int cb = cc0 & 63;
        const int hh = h + dy;
        const bool hok = ((unsigned)hh < 128u);
        const float* base = reg0 + (((size_t)n * 64 + cb) << 14) + (hh << 7);
#pragma unroll
        for (int i = 0; i < 8; i++) {
            int e  = tid + (i << 8);
            int m  = e & 127;
            int kp = e >> 7;
            int ww = m + dx;
            float f0 = 0.f, f1 = 0.f;
            if (hok && (unsigned)ww < 128u) {
                f0 = base[((size_t)(2 * kp)     << 14) + ww];
                f1 = base[((size_t)(2 * kp + 1) << 14) + ww];
            }
            __half2 h2 = __floats2half2_rn(f0, f1);
            areg[i] = *(uint32_t*)&h2;
        }
        const __half* wb = wt + kb * 32;
#pragma unroll
        for (int i = 0; i < 3; i++) {
            int idx = tid + (i << 8);
            int o = idx >> 2, q = idx & 3;
            breg[i] = *(const float4*)(wb + (size_t)o * KK + q * 8);
        }
    };

    auto sts_stage = [&](uint32_t sb) {
#pragma unroll
        for (int i = 0; i < 8; i++) {
            int e  = tid + (i << 8);
            int m  = e & 127;
            int kp = e >> 7;
            STS32(sb + m * AROW + kp * 4, areg[i]);
        }
        uint32_t bb = sb + STAGE_A;
#pragma unroll
        for (int i = 0; i < 3; i++) {
            int idx = tid + (i << 8);
            int o = idx >> 2, q = idx & 3;
            STS128(bb + o * AROW + q * 16,
                   __float_as_uint(breg[i].x), __float_as_uint(breg[i].y),
                   __float_as_uint(breg[i].z), __float_as_uint(breg[i].w));
        }
    };

    // ldmatrix lane addressing (constant per thread)
    const int a_row  = lane & 15;
    const int a_koff = (lane >> 4) * 16;          // bytes
    const int b_row  = (lane & 7) + ((lane >> 4) << 3);
    const int b_koff = ((lane >> 3) & 1) * 16;    // bytes

    auto do_mma = [&](uint32_t sb) {
        uint32_t ab = sb + (wm * 64 + a_row) * AROW + a_koff;
        uint32_t bb = sb + STAGE_A + (wn * 48 + b_row) * AROW + b_koff;
#pragma unroll
        for (int ks = 0; ks < 2; ks++) {
            uint32_t a[4][4];
#pragma unroll
            for (int mt = 0; mt < 4; mt++)
                LDMATRIX_X4(a[mt][0], a[mt][1], a[mt][2], a[mt][3],
                            ab + mt * (16 * AROW) + ks * 32);
            uint32_t bf[3][4];
#pragma unroll
            for (int bt = 0; bt < 3; bt++)
                LDMATRIX_X4(bf[bt][0], bf[bt][1], bf[bt][2], bf[bt][3],
                            bb + bt * (16 * AROW) + ks * 32);
#pragma unroll
            for (int mt = 0; mt < 4; mt++)
#pragma unroll
                for (int nt = 0; nt < 6; nt++)
                    MMA16816(c[mt][nt], a[mt],
                             bf[nt >> 1][(nt & 1) * 2],
                             bf[nt >> 1][(nt & 1) * 2 + 1]);
        }
    };

    // ---------------- main loop (double buffered) ----------------
    ldg_stage(0);
    sts_stage(sbase);
    __syncthreads();

    for (int kb = 0; kb < 36; kb++) {
        const uint32_t cur = sbase + (uint32_t)(kb & 1) * STAGE_SZ;
        const uint32_t nxt = sbase + (uint32_t)((kb & 1) ^ 1) * STAGE_SZ;
        if (kb < 35) ldg_stage(kb + 1);
        do_mma(cur);
        if (kb < 35) sts_stage(nxt);
        __syncthreads();
    }

    // ---------------- epilogue: C frags -> smem ----------------
    const int cw = lane >> 2;
    const int cn = (lane & 3) * 2;
#pragma unroll
    for (int mt = 0; mt < 4; mt++) {
#pragma unroll
        for (int nt = 0; nt < 6; nt++) {
            int w0  = wm * 64 + mt * 16 + cw;
            int ch0 = wn * 48 + nt * 8 + cn;
            sepi[w0 * EPI_STRIDE + ch0]           = c[mt][nt][0];
            sepi[w0 * EPI_STRIDE + ch0 + 1]       = c[mt][nt][1];
            sepi[(w0 + 8) * EPI_STRIDE + ch0]     = c[mt][nt][2];
            sepi[(w0 + 8) * EPI_STRIDE + ch0 + 1] = c[mt][nt][3];
        }
    }
    __syncthreads();

    // ---------------- gate + store ----------------
    const int wl  = tid & 31;
    const int ch0 = tid >> 5;     // 0..7
#pragma unroll
    for (int cq = 0; cq < 8; cq++) {
        const int ch = ch0 + cq * 8;
        const float bxr = bx[ch]       + bh[ch];
        const float bxz = bx[ch + 64]  + bh[ch + 64];
        const float bxn = bx[ch + 128];
        const float bhn = bh[ch + 128];
        float* orow = out + (((size_t)n * NC + ch) << 14) + (h << 7);
#pragma unroll
        for (int wc = 0; wc < 4; wc++) {
            const int w = wl + wc * 32;
            float xr = sepi[w * EPI_STRIDE + ch];
            float xz = sepi[w * EPI_STRIDE + ch + 64];
            float xn = sepi[w * EPI_STRIDE + ch + 128];
            float rg = 1.f / (1.f + expf(-(xr + bxr)));
            float zg = 1.f / (1.f + expf(-(xz + bxz)));
            float ng = tanhf(xn + bxn + rg * bhn);
            orow[w] = (1.f - zg) * ng;
        }
    }
}

// =========================================================================
extern "C" void kernel_launch(void* const* d_in, const int* in_sizes, int n_in,
                              void* d_out, int out_size)
{
    const float* feats = (const float*)d_in[0];   // [2,5,64,128,128]
    const float* trans = (const float*)d_in[1];   // [2,5,5,4,4]
    const float* wx    = (const float*)d_in[2];   // [192,128,3,3]
    const float* bx    = (const float*)d_in[4];   // [192]
    const float* bh    = (const float*)d_in[5];   // [192]
    float* out = (float*)d_out;                   // [2,5,64,128,128]

    float *pm, *pf;
    __half* pw;
    cudaGetSymbolAddress((void**)&pm, g_mean);
    cudaGetSymbolAddress((void**)&pf, g_feat);
    cudaGetSymbolAddress((void**)&pw, g_wt);

    const int smem1 = 2 * HH * 129 * (int)sizeof(float);
    cudaFuncSetAttribute(warp_mean_kernel,
                         cudaFuncAttributeMaxDynamicSharedMemorySize, smem1);
    cudaFuncSetAttribute(conv_gate_kernel,
                         cudaFuncAttributeMaxDynamicSharedMemorySize, CONV_SMEM);

    wtrans_kernel<<<(NO * KK + 255) / 256, 256>>>(wx, pw);

    for (int it = 0; it < 2; it++) {
        const float* fin  = (it == 0) ? feats : pf;
        float*       fout = (it == 1) ? out   : pf;

        warp_mean_kernel<<<dim3(NC, BA), 512, smem1>>>(fin, trans, pm);
        conv_gate_kernel<<<dim3(HH, BA), 256, CONV_SMEM>>>(
            fin, pm, pw, bx, bh, fout);
    }
}

// round 4
// speedup vs baseline: 5.8348x; 1.2117x over previous
#include <cuda_runtime.h>
#include <cuda_fp16.h>
#include <math.h>
#include <cstdint>

// Problem constants (V2VNet_35373350650590):
// B=2, A=5, C=64, H=W=128, gnn_iter=2
#define NB   2
#define NA   5
#define BA   10      // B*A
#define NC   64
#define HH   128
#define WW   128
#define HW   16384   // H*W
#define NO   192     // 3*C output channels of gate conv
#define KK   1152    // 2C * 9 reduction dim

// ---------------- static scratch (no allocations allowed) ----------------
__device__ float  g_mean[(size_t)BA * NC * HW];   // ~42 MB
__device__ float  g_feat[(size_t)BA * NC * HW];   // ~42 MB
__device__ __half g_wt  [(size_t)NO * KK];        // fp16 weights, permuted

// ======================= PTX helpers (portable) ==========================
__device__ __forceinline__ uint32_t smem_to_u32(const void* p) {
    uint32_t a;
    asm("{ .reg .u64 t; cvta.to.shared.u64 t, %1; cvt.u32.u64 %0, t; }"
        : "=r"(a) : "l"(p));
    return a;
}
#define LDMATRIX_X4(r0, r1, r2, r3, addr) \
    asm volatile("ldmatrix.sync.aligned.m8n8.x4.shared.b16 {%0,%1,%2,%3}, [%4];" \
        : "=r"(r0), "=r"(r1), "=r"(r2), "=r"(r3) : "r"(addr))
#define MMA16816(c, a, b0, b1) \
    asm volatile("mma.sync.aligned.m16n8k16.row.col.f32.f16.f16.f32 " \
        "{%0,%1,%2,%3}, {%4,%5,%6,%7}, {%8,%9}, {%0,%1,%2,%3};" \
        : "+f"((c)[0]), "+f"((c)[1]), "+f"((c)[2]), "+f"((c)[3]) \
        : "r"((a)[0]), "r"((a)[1]), "r"((a)[2]), "r"((a)[3]), \
          "r"(b0), "r"(b1))
#define STS32(addr, v) \
    asm volatile("st.shared.b32 [%0], %1;" :: "r"(addr), "r"(v) : "memory")
#define CP_ASYNC16(dst, src) \
    asm volatile("cp.async.cg.shared.global [%0], [%1], 16;" \
        :: "r"(dst), "l"(src) : "memory")
#define CP_COMMIT() asm volatile("cp.async.commit_group;" ::: "memory")
#define CP_WAIT0()  asm volatile("cp.async.wait_group 0;" ::: "memory")

// =========================================================================
// Kernel 0: weight permute + fp16 round.
// Row permutation groups r/z/n gates of the same channel block into one
// warp's N-tile: row' = (ch>>4)*48 + gate*16 + (ch&15), o = gate*64 + ch.
// K reordered tap-major: k' = tap*128 + cc.
// =========================================================================
__global__ __launch_bounds__(256)
void wtrans_kernel(const float* __restrict__ wx, __half* __restrict__ wt)
{
    int idx = blockIdx.x * 256 + threadIdx.x;
    if (idx >= NO * KK) return;
    int rowp = idx / KK;
    int kp   = idx - rowp * KK;
    int wn   = rowp / 48;
    int rem  = rowp - wn * 48;
    int gate = rem >> 4;
    int chl  = rem & 15;
    int o    = gate * 64 + wn * 16 + chl;
    int tap  = kp >> 7;
    int cc   = kp & 127;
    wt[idx] = __float2half_rn(wx[o * KK + cc * 9 + tap]);
}

// =========================================================================
// Kernel 1: warp (rotate then translate resample) + masked mean.
// Zero-border planes (131x131) replace per-sample masks: coords clamped to
// [-1, 128] in float; clamped-to-border samples read 0, and when both taps
// of an axis are out of range the fractional weight collapses to the border
// sample => exact zero-padding semantics with no compares/selects.
// =========================================================================
#define SW 131
__global__ __launch_bounds__(512, 1)
void warp_mean_kernel(const float* __restrict__ feats,
                      const float* __restrict__ trans,
                      float* __restrict__ meanb)
{
    const int c  = blockIdx.x;
    const int bi = blockIdx.y;
    const int b  = bi / NA;
    const int i  = bi - b * NA;

    extern __shared__ float sm[];
    float* s_src = sm;              // SW*SW, zero border
    float* s_f   = sm + SW * SW;    // SW*SW, zero border

    const int tid = threadIdx.x;

    // zero both planes once (borders persist; interiors get overwritten)
    for (int v = tid; v < 2 * SW * SW; v += 512) sm[v] = 0.f;
    __syncthreads();

    float acc[32];
#pragma unroll
    for (int k = 0; k < 32; k++) acc[k] = 0.f;

    for (int j = 0; j < NA; j++) {
        if (j == i) continue;
        const float* tp = trans + (size_t)(bi * NA + j) * 16;
        const float t00 = tp[0], t01 = tp[1], t03 = tp[3];
        const float t10 = tp[4], t11 = tp[5], t13 = tp[7];

        // ---- load source plane into interior ----
        const float* src = feats + ((size_t)(b * NA + j) * NC + c) * HW;
#pragma unroll
        for (int v = tid; v < HW / 4; v += 512) {
            float4 x = ((const float4*)src)[v];
            int r  = v >> 5;
            int c4 = (v & 31) << 2;
            float* d = s_src + (r + 1) * SW + c4 + 1;
            d[0] = x.x; d[1] = x.y; d[2] = x.z; d[3] = x.w;
        }
        __syncthreads();

        // ---- pass 1: rotation resample ----
#pragma unroll 4
        for (int k = 0; k < 32; k++) {
            int p = tid + (k << 9);
            int h = p >> 7, w = p & 127;
            float wf = (float)w - 63.5f;
            float hf = (float)h - 63.5f;
            float px = fmaf(t00, wf, fmaf(t01, hf, 63.5f));
            float py = fmaf(t10, wf, fmaf(t11, hf, 63.5f));
            px = fminf(fmaxf(px, -1.f), 128.f);
            py = fminf(fmaxf(py, -1.f), 128.f);
            float x0f = floorf(px), y0f = floorf(py);
            float fx = px - x0f, fy = py - y0f;
            int base = ((int)y0f + 1) * SW + (int)x0f + 1;
            float v00 = s_src[base];
            float v10 = s_src[base + 1];
            float v01 = s_src[base + SW];
            float v11 = s_src[base + SW + 1];
            float gx = 1.f - fx, gy = 1.f - fy;
            s_f[(h + 1) * SW + w + 1] =
                (v00 * gx + v10 * fx) * gy + (v01 * gx + v11 * fx) * fy;
        }
        __syncthreads();

        // ---- pass 2: constant-shift translate resample, accumulate ----
        const float tx = 2.f * t03;
        const float ty = -2.f * t13;
#pragma unroll 4
        for (int k = 0; k < 32; k++) {
            int p = tid + (k << 9);
            int h = p >> 7, w = p & 127;
            float px = fminf(fmaxf((float)w + tx, -1.f), 128.f);
            float py = fminf(fmaxf((float)h + ty, -1.f), 128.f);
            float x0f = floorf(px), y0f = floorf(py);
            float fx = px - x0f, fy = py - y0f;
            int base = ((int)y0f + 1) * SW + (int)x0f + 1;
            float v00 = s_f[base];
            float v10 = s_f[base + 1];
            float v01 = s_f[base + SW];
            float v11 = s_f[base + SW + 1];
            float gx = 1.f - fx, gy = 1.f - fy;
            acc[k] += (v00 * gx + v10 * fx) * gy + (v01 * gx + v11 * fx) * fy;
        }
        __syncthreads();
    }

    float* out = meanb + ((size_t)bi * NC + c) * HW;
#pragma unroll
    for (int k = 0; k < 32; k++)
        out[tid + (k << 9)] = acc[k] * 0.25f;
}

// =========================================================================
// Kernel 2: conv as implicit GEMM (fp16 mma.sync, fp32 accum) + fused
// ConvGRU gating, gating fully in registers (gate-interleaved weight rows).
// Per CTA: one image row h => D[128 px, 192 outch']. 36 stages of K=32,
// double-buffered; B staged via cp.async, A via ldg+cvt+sts.
// 8 warps: 2(m) x 4(n); warp tile 64 px x 48 ch' = {r,z,n} x 16 ch.
// =========================================================================
#define AROW      80u
#define STAGE_A   (128u * AROW)           // 10240
#define STAGE_B   (192u * AROW)           // 15360
#define STAGE_SZ  (STAGE_A + STAGE_B)     // 25600
#define CONV_SMEM (2 * STAGE_SZ)          // 51200

__global__ __launch_bounds__(256, 2)
void conv_gate_kernel(const float* __restrict__ feat,
                      const float* __restrict__ meanb,
                      const __half* __restrict__ wt,
                      const float* __restrict__ bx,
                      const float* __restrict__ bh,
                      float* __restrict__ out)
{
    extern __shared__ char smemraw[];
    const uint32_t sbase = smem_to_u32(smemraw);

    const int tid  = threadIdx.x;
    const int wid  = tid >> 5;
    const int lane = tid & 31;
    const int h = blockIdx.x;     // image row 0..127
    const int n = blockIdx.y;     // image 0..9

    const int wm = wid & 1;       // m(warp) -> w offset wm*64
    const int wn = wid >> 1;      // n(warp) -> channel block wn*16

    float c[4][6][4];
#pragma unroll
    for (int mt = 0; mt < 4; mt++)
#pragma unroll
        for (int nt = 0; nt < 6; nt++)
#pragma unroll
            for (int r = 0; r < 4; r++) c[mt][nt][r] = 0.f;

    uint32_t areg[8];

    auto ldgA = [&](int kb) {
        const int tap = kb >> 2;
        const int ty  = tap / 3;
        const int dy  = ty - 1;
        const int dx  = tap - ty * 3 - 1;
        const int cc0 = (kb & 3) * 32;
        const float* reg0 = (cc0 < 64) ? feat : meanb;
        const int cb = cc0 & 63;
        const int hh = h + dy;
        const bool hok = ((unsigned)hh < 128u);
        const float* base = reg0 + (((size_t)n * 64 + cb) << 14) + (hh << 7);
#pragma unroll
        for (int i = 0; i < 8; i++) {
            int e  = tid + (i << 8);
            int m  = e & 127;
            int kp = e >> 7;
            int ww = m + dx;
            float f0 = 0.f, f1 = 0.f;
            if (hok && (unsigned)ww < 128u) {
                f0 = base[((size_t)(2 * kp)     << 14) + ww];
                f1 = base[((size_t)(2 * kp + 1) << 14) + ww];
            }
            __half2 h2 = __floats2half2_rn(f0, f1);
            areg[i] = *(uint32_t*)&h2;
        }
    };
    auto stsA = [&](uint32_t sb) {
#pragma unroll
        for (int i = 0; i < 8; i++) {
            int e  = tid + (i << 8);
            int m  = e & 127;
            int kp = e >> 7;
            STS32(sb + m * AROW + kp * 4, areg[i]);
        }
    };
    auto cpB = [&](int kb, uint32_t sb) {
        const __half* wb = wt + kb * 32;
        uint32_t bb = sb + STAGE_A;
#pragma unroll
        for (int i = 0; i < 3; i++) {
            int idx = tid + (i << 8);
            int o = idx >> 2, q = idx & 3;
            CP_ASYNC16(bb + o * AROW + q * 16, wb + (size_t)o * KK + q * 8);
        }
    };

    // ldmatrix lane addressing
    const int a_row  = lane & 15;
    const int a_koff = (lane >> 4) * 16;
    const int b_row  = (lane & 7) + ((lane >> 4) << 3);
    const int b_koff = ((lane >> 3) & 1) * 16;

    auto do_mma = [&](uint32_t sb) {
        uint32_t ab = sb + (wm * 64 + a_row) * AROW + a_koff;
        uint32_t bb = sb + STAGE_A + (wn * 48 + b_row) * AROW + b_koff;
#pragma unroll
        for (int ks = 0; ks < 2; ks++) {
            uint32_t bf[3][4];
#pragma unroll
            for (int bt = 0; bt < 3; bt++)
                LDMATRIX_X4(bf[bt][0], bf[bt][1], bf[bt][2], bf[bt][3],
                            bb + bt * (16 * AROW) + ks * 32);
#pragma unroll
            for (int mt = 0; mt < 4; mt++) {
                uint32_t a[4];
                LDMATRIX_X4(a[0], a[1], a[2], a[3],
                            ab + mt * (16 * AROW) + ks * 32);
#pragma unroll
                for (int nt = 0; nt < 6; nt++)
                    MMA16816(c[mt][nt], a,
                             bf[nt >> 1][(nt & 1) * 2],
                             bf[nt >> 1][(nt & 1) * 2 + 1]);
            }
        }
    };

    // ---------------- main loop (double buffered) ----------------
    ldgA(0); stsA(sbase);
    cpB(0, sbase); CP_COMMIT(); CP_WAIT0();
    __syncthreads();

    for (int kb = 0; kb < 36; kb++) {
        const uint32_t cur = sbase + (uint32_t)(kb & 1) * STAGE_SZ;
        const uint32_t nxt = sbase + (uint32_t)((kb & 1) ^ 1) * STAGE_SZ;
        if (kb < 35) { ldgA(kb + 1); cpB(kb + 1, nxt); CP_COMMIT(); }
        do_mma(cur);
        if (kb < 35) { stsA(nxt); CP_WAIT0(); }
        __syncthreads();
    }

    // ---------------- epilogue: gate in registers, store ----------------
    // nt = gate*2 + half; fragment (k): k0,k1 -> row cw, cols cn,cn+1;
    //                                  k2,k3 -> row cw+8.
    const int cw = lane >> 2;
    const int cn = (lane & 3) * 2;
#pragma unroll
    for (int half = 0; half < 2; half++) {
#pragma unroll
        for (int q = 0; q < 2; q++) {
            const int ch = wn * 16 + half * 8 + cn + q;
            const float bxr = bx[ch]       + bh[ch];
            const float bxz = bx[ch + 64]  + bh[ch + 64];
            const float bxn = bx[ch + 128];
            const float bhn = bh[ch + 128];
            float* orow = out + (((size_t)n * NC + ch) << 14) + (h << 7);
#pragma unroll
            for (int mt = 0; mt < 4; mt++) {
#pragma unroll
                for (int rr = 0; rr < 2; rr++) {
                    const int k = rr * 2 + q;
                    const int w = wm * 64 + mt * 16 + cw + rr * 8;
                    float xr = c[mt][0 + half][k];
                    float xz = c[mt][2 + half][k];
                    float xn = c[mt][4 + half][k];
                    float rg = 1.f / (1.f + expf(-(xr + bxr)));
                    float zg = 1.f / (1.f + expf(-(xz + bxz)));
                    float ng = tanhf(xn + bxn + rg * bhn);
                    orow[w] = (1.f - zg) * ng;
                }
            }
        }
    }
}

// =========================================================================
extern "C" void kernel_launch(void* const* d_in, const int* in_sizes, int n_in,
                              void* d_out, int out_size)
{
    const float* feats = (const float*)d_in[0];   // [2,5,64,128,128]
    const float* trans = (const float*)d_in[1];   // [2,5,5,4,4]
    const float* wx    = (const float*)d_in[2];   // [192,128,3,3]
    const float* bx    = (const float*)d_in[4];   // [192]
    const float* bh    = (const float*)d_in[5];   // [192]
    float* out = (float*)d_out;                   // [2,5,64,128,128]

    float *pm, *pf;
    __half* pw;
    cudaGetSymbolAddress((void**)&pm, g_mean);
    cudaGetSymbolAddress((void**)&pf, g_feat);
    cudaGetSymbolAddress((void**)&pw, g_wt);

    const int smem1 = 2 * SW * SW * (int)sizeof(float);   // 137288
    cudaFuncSetAttribute(warp_mean_kernel,
                         cudaFuncAttributeMaxDynamicSharedMemorySize, smem1);
    cudaFuncSetAttribute(conv_gate_kernel,
                         cudaFuncAttributeMaxDynamicSharedMemorySize, CONV_SMEM);

    wtrans_kernel<<<(NO * KK + 255) / 256, 256>>>(wx, pw);

    for (int it = 0; it < 2; it++) {
        const float* fin  = (it == 0) ? feats : pf;
        float*       fout = (it == 1) ? out   : pf;

        warp_mean_kernel<<<dim3(NC, BA), 512, smem1>>>(fin, trans, pm);
        conv_gate_kernel<<<dim3(HH, BA), 256, CONV_SMEM>>>(
            fin, pm, pw, bx, bh, fout);
    }
}